// round 14
// baseline (speedup 1.0000x reference)
#include <cuda_runtime.h>

typedef unsigned long long ull;

#define NP 16          // column partitions
#define NBLK 128       // 8 gpairs x 16 p
#define NT 256         // 8 warps
// smem floats: sWA 12800 + sWB 25600 + 4 h tiles (4x4096) + red2 128 + ybuf 16
#define SM_FLOATS (12800+25600+16384+128+16)
#define SMEM_BYTES (SM_FLOATS*4)

// ---------------- static device scratch (no allocation) ----------------
__device__ float d_pA[NP*256*50];      // W_hh0 packed  [p][k(stride50)][cp][gate*2+cl]
__device__ float d_pB[NP*256*100];     // W_ih1|W_hh1   [p][k(stride100)][cp][gate*4+s*2+cl]
__device__ float d_pD[NP*256*50];      // Wd_hh packed like A
__device__ float d_xT[512*256];        // x transposed [t][b]
__device__ float d_h0g[2*16*4096];     // [par][group16][col256][b16]
__device__ float d_h1g[2*16*4096];
__device__ float d_party[2*16*16*16];  // [par][p][group][b]
__device__ unsigned int d_cnt[16];     // per-group barrier counters

// ---------------- prep ----------------
__global__ void prep_kernel(const float* __restrict__ Whh0, const float* __restrict__ Wih1,
                            const float* __restrict__ Whh1, const float* __restrict__ Wdhh,
                            const float* __restrict__ x)
{
    int idx = blockIdx.x*blockDim.x + threadIdx.x;
    int stride = gridDim.x*blockDim.x;
    if (idx < 16) d_cnt[idx] = 0u;
    for (int i = idx; i < NP*256*48; i += stride) {
        int q = i % 6, cp = (i/6) & 7, k = (i/48) & 255, pp = i/12288;
        int gate = q >> 1, cl = q & 1;
        int col = pp*16 + cp*2 + cl;
        int src = (gate*256 + col)*256 + k;
        int dst = pp*12800 + k*50 + cp*6 + q;
        d_pA[dst] = Whh0[src];
        d_pD[dst] = Wdhh[src];
    }
    for (int i = idx; i < NP*256*96; i += stride) {
        int q = i % 12, cp = (i/12) & 7, k = (i/96) & 255, pp = i/24576;
        int gate = q >> 2, s = (q >> 1) & 1, cl = q & 1;
        int col = pp*16 + cp*2 + cl;
        int src = (gate*256 + col)*256 + k;
        d_pB[pp*25600 + k*100 + cp*12 + q] = s ? Whh1[src] : Wih1[src];
    }
    for (int i = idx; i < 512*256; i += stride)
        d_xT[i] = x[(i & 255)*512 + (i >> 8)];
    for (int i = idx; i < 2*16*4096; i += stride)
        d_h1g[i] = 0.0f;   // first h1 refresh must read zeros
}

// ---------------- helpers ----------------
__device__ __forceinline__ ull splat2(float v){ ull r; asm("mov.b64 %0, {%1,%1};" : "=l"(r) : "f"(v)); return r; }
__device__ __forceinline__ void fma2(ull &d, ull a, ull b){ asm("fma.rn.f32x2 %0, %1, %2, %0;" : "+l"(d) : "l"(a), "l"(b)); }
__device__ __forceinline__ ull add2(ull a, ull b){ ull r; asm("add.rn.f32x2 %0, %1, %2;" : "=l"(r) : "l"(a), "l"(b)); return r; }
__device__ __forceinline__ float2 unp(ull v){ float2 f; asm("mov.b64 {%0,%1}, %2;" : "=f"(f.x), "=f"(f.y) : "l"(v)); return f; }
__device__ __forceinline__ float sigf(float v){ return 1.0f/(1.0f + __expf(-v)); }
__device__ __forceinline__ float tanh_(float v){
    float a = fabsf(v), e = __expf(-2.0f*a);
    float t = (1.0f - e)/(1.0f + e);
    return v < 0.0f ? -t : t;
}
// reduce over kh (lane bits 3,4): fixed order ((0+1)+(2+3))
__device__ __forceinline__ ull shred(ull v){
    v = add2(v, __shfl_xor_sync(0xffffffffu, v, 8));
    v = add2(v, __shfl_xor_sync(0xffffffffu, v, 16));
    return v;
}
// split barrier: arrive (release) / wait (acquire)
__device__ __forceinline__ void garrive(int gi){
    __threadfence();
    __syncthreads();
    if (threadIdx.x == 0) atomicAdd(&d_cnt[gi], 1u);
}
__device__ __forceinline__ void gwait(int gi, unsigned target){
    if (threadIdx.x == 0) {
        while (*(volatile unsigned*)&d_cnt[gi] < target) __nanosleep(16);
        __threadfence();
    }
    __syncthreads();
}

// ---------------- main persistent kernel ----------------
__global__ __launch_bounds__(NT, 1) void gru_main(
    const float* __restrict__ Wih0, const float* __restrict__ bih0, const float* __restrict__ bhh0,
    const float* __restrict__ bih1, const float* __restrict__ bhh1,
    const float* __restrict__ Wdih, const float* __restrict__ bdih, const float* __restrict__ bdhh,
    const float* __restrict__ Wo, const float* __restrict__ bo,
    float* __restrict__ out)
{
    extern __shared__ float sm[];
    float* sWA = sm;               // [256][50]  (8cp x 6 used)
    float* sWB = sm + 12800;       // [256][100] (8cp x 12 used)
    float* hA0 = sWB + 25600;      // [256 col][16 b]
    float* hA1 = hA0 + 4096;
    float* hB0 = hA1 + 4096;
    float* hB1 = hB0 + 4096;
    float* red2 = hB1 + 4096;      // [16 b][8 cp]
    float* ybuf = red2 + 128;      // [16]

    const int p     = blockIdx.x & 15;
    const int gpair = blockIdx.x >> 4;
    const int tid   = threadIdx.x;
    const int cp    = tid >> 5;
    const int lane  = tid & 31;
    const int kh    = lane >> 3;          // k offset 0..3 (k = kh + 4*kk)
    const int bq    = lane & 7;           // batch pair 0..7 (2 batches each)
    const int c0    = p*16 + cp*2;
    const int bl    = kh & 1;             // epilogue cell: batch slot
    const int cl    = kh >> 1;            // epilogue cell: column slot
    const int bidx  = bq*2 + bl;
    const int col_e = c0 + cl;

    float* h0sg[2] = {hA0, hB0};
    float* h1sg[2] = {hA1, hB1};

    // stage weights, zero h tiles
    {
        const float4* a4 = (const float4*)(d_pA + p*12800);
        float4* da = (float4*)sWA;
        for (int i = tid; i < 3200; i += NT) da[i] = a4[i];
        const float4* b4 = (const float4*)(d_pB + p*25600);
        float4* db = (float4*)sWB;
        for (int i = tid; i < 6400; i += NT) db[i] = b4[i];
        float4 z = make_float4(0.f, 0.f, 0.f, 0.f);
        float4* zt = (float4*)hA0;
        for (int i = tid; i < 4096; i += NT) zt[i] = z;   // all 4 tiles contiguous
    }

    // per-lane gate constants (only this lane's column slice)
    const float wi0r = Wih0[col_e], wi0z = Wih0[256 + col_e], wi0n = Wih0[512 + col_e];
    const float bi0r = bih0[col_e], bi0z = bih0[256 + col_e], bi0n = bih0[512 + col_e];
    const float bh0r = bhh0[col_e], bh0z = bhh0[256 + col_e], bh0n = bhh0[512 + col_e];
    const float bi1r = bih1[col_e], bi1z = bih1[256 + col_e], bi1n = bih1[512 + col_e];
    const float bh1r = bhh1[col_e], bh1z = bhh1[256 + col_e], bh1n = bhh1[512 + col_e];
    __syncthreads();

    // ================= encoder: 512 iters x 2 groups, pipelined =================
    for (int u = 0; u < 512; u++) {
#pragma unroll
        for (int grp = 0; grp < 2; grp++) {
            const int gX = gpair*2 + grp;
            float* h0s = h0sg[grp];
            float* h1s = h1sg[grp];
            if (u > 0) {
                gwait(gX, 16u*(unsigned)u);
                const float4* s0 = (const float4*)(d_h0g + ((((u-1)&1)*16 + gX) << 12));
                const float4* s1 = (const float4*)(d_h1g + ((((u-1)&1)*16 + gX) << 12));
                float4* dd0 = (float4*)h0s;
                float4* dd1 = (float4*)h1s;
                for (int i = tid; i < 1024; i += NT) { dd0[i] = __ldcg(s0 + i); dd1[i] = __ldcg(s1 + i); }
                __syncthreads();
            }
            float xv = d_xT[u*256 + gX*16 + bidx];

            ull aA[6], aI[6], aH[6];
#pragma unroll
            for (int i = 0; i < 6; i++) { aA[i] = 0ull; aI[i] = 0ull; aH[i] = 0ull; }
            {
                const float* h0p = h0s + bq*2 + kh*16;
                const float* h1p = h1s + bq*2 + kh*16;
                const float* wap = sWA + kh*50  + cp*6;
                const float* wbp = sWB + kh*100 + cp*12;
#pragma unroll 4
                for (int kk = 0; kk < 64; kk++) {
                    float2 u2 = *(const float2*)h0p;
                    float2 v2 = *(const float2*)h1p;
                    ull hx0 = splat2(u2.x), hx1 = splat2(u2.y);
                    ull vx0 = splat2(v2.x), vx1 = splat2(v2.y);
                    const ull* wa = (const ull*)wap;
                    ull a0 = wa[0], a1 = wa[1], a2 = wa[2];
                    const ulonglong2* wb = (const ulonglong2*)wbp;
                    ulonglong2 w0 = wb[0], w1 = wb[1], w2 = wb[2];
                    fma2(aA[0], a0, hx0);   fma2(aA[1], a0, hx1);
                    fma2(aA[2], a1, hx0);   fma2(aA[3], a1, hx1);
                    fma2(aA[4], a2, hx0);   fma2(aA[5], a2, hx1);
                    fma2(aI[0], w0.x, hx0); fma2(aI[1], w0.x, hx1);
                    fma2(aI[2], w1.x, hx0); fma2(aI[3], w1.x, hx1);
                    fma2(aI[4], w2.x, hx0); fma2(aI[5], w2.x, hx1);
                    fma2(aH[0], w0.y, vx0); fma2(aH[1], w0.y, vx1);
                    fma2(aH[2], w1.y, vx0); fma2(aH[3], w1.y, vx1);
                    fma2(aH[4], w2.y, vx0); fma2(aH[5], w2.y, vx1);
                    h0p += 64; h1p += 64; wap += 200; wbp += 400;
                }
            }
#pragma unroll
            for (int i = 0; i < 6; i++) { aA[i] = shred(aA[i]); aI[i] = shred(aI[i]); aH[i] = shred(aH[i]); }

            // ---- epilogue: every lane owns one GRU cell (bl, cl) ----
            {   // layer 0 -> h0(u+1)
                float2 fr = unp(aA[bl]), fz = unp(aA[2+bl]), fn = unp(aA[4+bl]);
                float gr = (cl ? fr.y : fr.x) + bh0r;
                float gz = (cl ? fz.y : fz.x) + bh0z;
                float gn = (cl ? fn.y : fn.x) + bh0n;
                float r  = sigf(xv*wi0r + bi0r + gr);
                float z  = sigf(xv*wi0z + bi0z + gz);
                float n  = tanh_(xv*wi0n + bi0n + r*gn);
                float hold = h0s[col_e*16 + bidx];
                d_h0g[(((u&1)*16 + gX) << 12) + col_e*16 + bidx] = (1.0f - z)*n + z*hold;
            }
            if (u != 0) {   // layer 1 -> h1(u)
                float2 fir = unp(aI[bl]), fiz = unp(aI[2+bl]), fin = unp(aI[4+bl]);
                float2 fhr = unp(aH[bl]), fhz = unp(aH[2+bl]), fhn = unp(aH[4+bl]);
                float r  = sigf((cl ? fir.y : fir.x) + bi1r + (cl ? fhr.y : fhr.x) + bh1r);
                float z  = sigf((cl ? fiz.y : fiz.x) + bi1z + (cl ? fhz.y : fhz.x) + bh1z);
                float n  = tanh_((cl ? fin.y : fin.x) + bi1n + r*((cl ? fhn.y : fhn.x) + bh1n));
                float hold = h1s[col_e*16 + bidx];
                d_h1g[(((u&1)*16 + gX) << 12) + col_e*16 + bidx] = (1.0f - z)*n + z*hold;
            }
            garrive(gX);
        }
    }

    // ================= drain (iter 512): layer-1 step 511 =================
#pragma unroll
    for (int grp = 0; grp < 2; grp++) {
        const int gX = gpair*2 + grp;
        float* h0s = h0sg[grp];
        float* h1s = h1sg[grp];
        gwait(gX, 16u*512u);
        {
            const float4* s0 = (const float4*)(d_h0g + ((1*16 + gX) << 12));   // par 511&1=1
            const float4* s1 = (const float4*)(d_h1g + ((1*16 + gX) << 12));
            float4* dd0 = (float4*)h0s;
            float4* dd1 = (float4*)h1s;
            for (int i = tid; i < 1024; i += NT) { dd0[i] = __ldcg(s0 + i); dd1[i] = __ldcg(s1 + i); }
            __syncthreads();
        }
        ull aI[6], aH[6];
#pragma unroll
        for (int i = 0; i < 6; i++) { aI[i] = 0ull; aH[i] = 0ull; }
        {
            const float* h0p = h0s + bq*2 + kh*16;
            const float* h1p = h1s + bq*2 + kh*16;
            const float* wbp = sWB + kh*100 + cp*12;
#pragma unroll 4
            for (int kk = 0; kk < 64; kk++) {
                float2 u2 = *(const float2*)h0p;
                float2 v2 = *(const float2*)h1p;
                ull hx0 = splat2(u2.x), hx1 = splat2(u2.y);
                ull vx0 = splat2(v2.x), vx1 = splat2(v2.y);
                const ulonglong2* wb = (const ulonglong2*)wbp;
                ulonglong2 w0 = wb[0], w1 = wb[1], w2 = wb[2];
                fma2(aI[0], w0.x, hx0); fma2(aI[1], w0.x, hx1);
                fma2(aI[2], w1.x, hx0); fma2(aI[3], w1.x, hx1);
                fma2(aI[4], w2.x, hx0); fma2(aI[5], w2.x, hx1);
                fma2(aH[0], w0.y, vx0); fma2(aH[1], w0.y, vx1);
                fma2(aH[2], w1.y, vx0); fma2(aH[3], w1.y, vx1);
                fma2(aH[4], w2.y, vx0); fma2(aH[5], w2.y, vx1);
                h0p += 64; h1p += 64; wbp += 400;
            }
        }
#pragma unroll
        for (int i = 0; i < 6; i++) { aI[i] = shred(aI[i]); aH[i] = shred(aH[i]); }
        {
            float2 fir = unp(aI[bl]), fiz = unp(aI[2+bl]), fin = unp(aI[4+bl]);
            float2 fhr = unp(aH[bl]), fhz = unp(aH[2+bl]), fhn = unp(aH[4+bl]);
            float r  = sigf((cl ? fir.y : fir.x) + bi1r + (cl ? fhr.y : fhr.x) + bh1r);
            float z  = sigf((cl ? fiz.y : fiz.x) + bi1z + (cl ? fhz.y : fhz.x) + bh1z);
            float n  = tanh_((cl ? fin.y : fin.x) + bi1n + r*((cl ? fhn.y : fhn.x) + bh1n));
            float hold = h1s[col_e*16 + bidx];
            d_h1g[((0*16 + gX) << 12) + col_e*16 + bidx] = (1.0f - z)*n + z*hold;   // par 512&1=0
        }
        garrive(gX);
    }

    // ================= decoder setup =================
    {
        const float4* a4 = (const float4*)(d_pD + p*12800);
        float4* da = (float4*)sWA;
        for (int i = tid; i < 3200; i += NT) da[i] = a4[i];
    }
    const float wdr = Wdih[col_e], wdz = Wdih[256 + col_e], wdn = Wdih[512 + col_e];
    const float bdr = bdih[col_e], bdz = bdih[256 + col_e], bdn = bdih[512 + col_e];
    const float bhr = bdhh[col_e], bhz = bdhh[256 + col_e], bhn = bdhh[512 + col_e];
    const float woc = Wo[col_e];
    const float bov = bo[0];
    __syncthreads();

    // ================= decoder: 96 iters x 2 groups, pipelined =================
    for (int t = 0; t < 96; t++) {
#pragma unroll
        for (int grp = 0; grp < 2; grp++) {
            const int gX = gpair*2 + grp;
            float* h1s = h1sg[grp];
            gwait(gX, 16u*(unsigned)(513 + t));
            {   // refresh h1 (par = t&1) + y reduction for step t-1
                const float4* s1 = (const float4*)(d_h1g + ((((t&1)*16) + gX) << 12));
                float4* dd1 = (float4*)h1s;
                for (int i = tid; i < 1024; i += NT) dd1[i] = __ldcg(s1 + i);
                if (t > 0 && tid < 16) {
                    float s = bov;
#pragma unroll
                    for (int q = 0; q < 16; q++)
                        s += __ldcg(&d_party[(((t&1)*16 + q)*16 + gX)*16 + tid]);
                    ybuf[tid] = s;
                    if (p == 0) out[(gX*16 + tid)*96 + (t-1)] = s;
                }
                __syncthreads();
            }
            float inp = (t > 0) ? ybuf[bidx] : 0.0f;

            ull aD[6];
#pragma unroll
            for (int i = 0; i < 6; i++) aD[i] = 0ull;
            {
                const float* h1p = h1s + bq*2 + kh*16;
                const float* wap = sWA + kh*50 + cp*6;
#pragma unroll 4
                for (int kk = 0; kk < 64; kk++) {
                    float2 v2 = *(const float2*)h1p;
                    ull vx0 = splat2(v2.x), vx1 = splat2(v2.y);
                    const ull* wa = (const ull*)wap;
                    ull a0 = wa[0], a1 = wa[1], a2 = wa[2];
                    fma2(aD[0], a0, vx0); fma2(aD[1], a0, vx1);
                    fma2(aD[2], a1, vx0); fma2(aD[3], a1, vx1);
                    fma2(aD[4], a2, vx0); fma2(aD[5], a2, vx1);
                    h1p += 64; wap += 200;
                }
            }
#pragma unroll
            for (int i = 0; i < 6; i++) aD[i] = shred(aD[i]);

            {   // epilogue cell
                float2 fr = unp(aD[bl]), fz = unp(aD[2+bl]), fn = unp(aD[4+bl]);
                float gr = (cl ? fr.y : fr.x) + bhr;
                float gz = (cl ? fz.y : fz.x) + bhz;
                float gn = (cl ? fn.y : fn.x) + bhn;
                float r  = sigf(inp*wdr + bdr + gr);
                float z  = sigf(inp*wdz + bdz + gz);
                float n  = tanh_(inp*wdn + bdn + r*gn);
                float hold = h1s[col_e*16 + bidx];
                float hv = (1.0f - z)*n + z*hold;
                d_h1g[((((t+1)&1)*16 + gX) << 12) + col_e*16 + bidx] = hv;
                float pypart = hv * woc;
                float py = pypart + __shfl_xor_sync(0xffffffffu, pypart, 16);  // add other column slot
                if (cl == 0) red2[bidx*8 + cp] = py;
            }
            __syncthreads();
            if (tid < 16) {   // partial over this CTA's 16 cols (fixed order)
                float s = 0.f;
#pragma unroll
                for (int j = 0; j < 8; j++) s += red2[tid*8 + j];
                d_party[((((t+1)&1)*16 + p)*16 + gX)*16 + tid] = s;
            }
            garrive(gX);
        }
    }

    // final outputs (t = 95)
#pragma unroll
    for (int grp = 0; grp < 2; grp++) {
        const int gX = gpair*2 + grp;
        gwait(gX, 16u*609u);
        if (p == 0 && tid < 16) {
            float s = bov;
#pragma unroll
            for (int q = 0; q < 16; q++)
                s += __ldcg(&d_party[((0*16 + q)*16 + gX)*16 + tid]);   // par (95+1)&1 = 0
            out[(gX*16 + tid)*96 + 95] = s;
        }
    }
}

// ---------------- launch ----------------
extern "C" void kernel_launch(void* const* d_in, const int* in_sizes, int n_in,
                              void* d_out, int out_size)
{
    const float* x    = (const float*)d_in[0];
    const float* Wih0 = (const float*)d_in[1];
    const float* Whh0 = (const float*)d_in[2];
    const float* bih0 = (const float*)d_in[3];
    const float* bhh0 = (const float*)d_in[4];
    const float* Wih1 = (const float*)d_in[5];
    const float* Whh1 = (const float*)d_in[6];
    const float* bih1 = (const float*)d_in[7];
    const float* bhh1 = (const float*)d_in[8];
    const float* Wdih = (const float*)d_in[9];
    const float* Wdhh = (const float*)d_in[10];
    const float* bdih = (const float*)d_in[11];
    const float* bdhh = (const float*)d_in[12];
    const float* Wo   = (const float*)d_in[13];
    const float* bo   = (const float*)d_in[14];
    float* out = (float*)d_out;

    cudaFuncSetAttribute(gru_main, cudaFuncAttributeMaxDynamicSharedMemorySize, SMEM_BYTES);
    prep_kernel<<<384, 256>>>(Whh0, Wih1, Whh1, Wdhh, x);
    gru_main<<<NBLK, NT, SMEM_BYTES>>>(Wih0, bih0, bhh0, bih1, bhh1,
                                       Wdih, bdih, bdhh, Wo, bo, out);
}

// round 15
// speedup vs baseline: 1.3115x; 1.3115x over previous
#include <cuda_runtime.h>

typedef unsigned long long ull;

#define NG 8           // batch groups (32 batches each)
#define NP 16          // column partitions (16 hidden cols each)
#define NBLK (NG*NP)   // 128 CTAs
#define NT 256         // 8 warps
// smem floats: sP1 25600 + sP2 12800 + h0s 8192 + h1s 8192 + red2 256 + ybuf 32
#define SM_FLOATS (25600+12800+8192+8192+256+32)
#define SMEM_BYTES (SM_FLOATS*4)

// ---------------- static device scratch (no allocation) ----------------
__device__ float d_pP1[NP*256*100];   // [p][k(str100)][cp][ Whh0 r0 r1 z0 z1 n0 n1 | Wih1 r0 r1 z0 z1 n0 n1 ]
__device__ float d_pP2[NP*256*50];    // [p][k(str50)][cp][ Whh1 r0 r1 z0 z1 n0 n1 ]
__device__ float d_pD [NP*256*50];    // Wd_hh, same layout as P2
__device__ float d_xT[512*256];       // x transposed [t][b]
__device__ float d_h0g[2*NG*8192];    // [par][g][col256][b32]
__device__ float d_h1g[2*NG*8192];
__device__ float d_party[2*NP*NG*32]; // [par][p][g][b]
__device__ unsigned int d_cnt[NG];    // group barrier counters

// ---------------- prep ----------------
__global__ void prep_kernel(const float* __restrict__ Whh0, const float* __restrict__ Wih1,
                            const float* __restrict__ Whh1, const float* __restrict__ Wdhh,
                            const float* __restrict__ x)
{
    int idx = blockIdx.x*blockDim.x + threadIdx.x;
    int stride = gridDim.x*blockDim.x;
    if (idx < NG) d_cnt[idx] = 0u;
    for (int i = idx; i < NP*256*96; i += stride) {
        int q = i % 12, cp = (i/12) & 7, k = (i/96) & 255, p = i/24576;
        int qq = (q < 6) ? q : q - 6;
        int gate = qq >> 1, cl = qq & 1;
        int col = p*16 + cp*2 + cl;
        int src = (gate*256 + col)*256 + k;
        d_pP1[p*25600 + k*100 + cp*12 + q] = (q < 6) ? Whh0[src] : Wih1[src];
    }
    for (int i = idx; i < NP*256*48; i += stride) {
        int q = i % 6, cp = (i/6) & 7, k = (i/48) & 255, p = i/12288;
        int gate = q >> 1, cl = q & 1;
        int col = p*16 + cp*2 + cl;
        int src = (gate*256 + col)*256 + k;
        int dst = p*12800 + k*50 + cp*6 + q;
        d_pP2[dst] = Whh1[src];
        d_pD[dst]  = Wdhh[src];
    }
    for (int i = idx; i < 512*256; i += stride)
        d_xT[i] = x[(i & 255)*512 + (i >> 8)];
    for (int i = idx; i < 2*NG*8192; i += stride)
        d_h1g[i] = 0.0f;   // phase-1 h1 refresh must read zeros
}

// ---------------- helpers ----------------
__device__ __forceinline__ ull splat2(float v){ ull r; asm("mov.b64 %0, {%1,%1};" : "=l"(r) : "f"(v)); return r; }
__device__ __forceinline__ void fma2(ull &d, ull a, ull b){ asm("fma.rn.f32x2 %0, %1, %2, %0;" : "+l"(d) : "l"(a), "l"(b)); }
__device__ __forceinline__ ull add2(ull a, ull b){ ull r; asm("add.rn.f32x2 %0, %1, %2;" : "=l"(r) : "l"(a), "l"(b)); return r; }
__device__ __forceinline__ float2 unp(ull v){ float2 f; asm("mov.b64 {%0,%1}, %2;" : "=f"(f.x), "=f"(f.y) : "l"(v)); return f; }
__device__ __forceinline__ float sigf(float v){ return 1.0f/(1.0f + __expf(-v)); }
__device__ __forceinline__ float tanh_(float v){
    float a = fabsf(v), e = __expf(-2.0f*a);
    float t = (1.0f - e)/(1.0f + e);
    return v < 0.0f ? -t : t;
}
// reduce over kh (lane bits 3,4): fixed order
__device__ __forceinline__ ull shred(ull v){
    v = add2(v, __shfl_xor_sync(0xffffffffu, v, 8));
    v = add2(v, __shfl_xor_sync(0xffffffffu, v, 16));
    return v;
}
__device__ __forceinline__ unsigned s2u(const void* p){
    unsigned a;
    asm("{ .reg .u64 t; cvta.to.shared.u64 t, %1; cvt.u32.u64 %0, t; }" : "=r"(a) : "l"(p));
    return a;
}
#define CP16(dst, src) asm volatile("cp.async.cg.shared.global [%0], [%1], 16;" :: "r"(dst), "l"(src) : "memory")
#define CPCOMMIT()     asm volatile("cp.async.commit_group;" ::: "memory")
#define CPWAIT(n)      asm volatile("cp.async.wait_group %0;" :: "n"(n) : "memory")

// leader-release barrier (cooperative-groups grid.sync pattern)
__device__ __forceinline__ void garrive(int g){
    __syncthreads();
    if (threadIdx.x == 0)
        asm volatile("red.release.gpu.global.add.u32 [%0], %1;" :: "l"(d_cnt + g), "r"(1u) : "memory");
}
__device__ __forceinline__ void gwait(int g, unsigned target){
    if (threadIdx.x == 0) {
        unsigned v;
        do {
            asm volatile("ld.acquire.gpu.global.u32 %0, [%1];" : "=r"(v) : "l"(d_cnt + g) : "memory");
        } while (v < target);
    }
    __syncthreads();
}

// ---------------- main persistent kernel ----------------
__global__ __launch_bounds__(NT, 1) void gru_main(
    const float* __restrict__ Wih0, const float* __restrict__ bih0, const float* __restrict__ bhh0,
    const float* __restrict__ bih1, const float* __restrict__ bhh1,
    const float* __restrict__ Wdih, const float* __restrict__ bdih, const float* __restrict__ bdhh,
    const float* __restrict__ Wo, const float* __restrict__ bo,
    float* __restrict__ out)
{
    extern __shared__ float sm[];
    float* sP1 = sm;               // [256][100] (8cp x 12 used: A6 | I6)
    float* sP2 = sm + 25600;       // [256][50]  (8cp x 6 used: Whh1 / later Wd_hh)
    float* h0s = sP2 + 12800;      // [256 col][32 b]
    float* h1s = h0s + 8192;
    float* red2 = h1s + 8192;      // [32 b][8 cp]
    float* ybuf = red2 + 256;      // [32]

    const int p    = blockIdx.x & 15;
    const int g    = blockIdx.x >> 4;
    const int tid  = threadIdx.x;
    const int cp   = tid >> 5;
    const int lane = tid & 31;
    const int bq   = lane & 7;            // batch quad 0..7 (4 batches)
    const int kh   = lane >> 3;           // k offset 0..3 (k = kh + 4*kk)
    const int c0   = p*16 + cp*2;
    const bool epi = (kh == 0);

    const unsigned h0u = s2u(h0s);
    const unsigned h1u = s2u(h1s);

    // stage weights + zero h tiles
    {
        const float4* a4 = (const float4*)(d_pP1 + p*25600);
        float4* da = (float4*)sP1;
        for (int i = tid; i < 6400; i += NT) da[i] = a4[i];
        const float4* b4 = (const float4*)(d_pP2 + p*12800);
        float4* db = (float4*)sP2;
        for (int i = tid; i < 3200; i += NT) db[i] = b4[i];
        float4 z = make_float4(0.f, 0.f, 0.f, 0.f);
        float4* zt = (float4*)h0s;
        for (int i = tid; i < 4096; i += NT) zt[i] = z;   // h0s + h1s contiguous
    }

    // per-thread gate constants; q = gate*2 + cl
    float wi0[6], bi0[6], bh0[6], bi1c[6], bh1c[6];
#pragma unroll
    for (int q = 0; q < 6; q++) {
        int j = (q >> 1)*256 + c0 + (q & 1);
        wi0[q] = Wih0[j]; bi0[q] = bih0[j]; bh0[q] = bhh0[j];
        bi1c[q] = bih1[j]; bh1c[q] = bhh1[j];
    }
    __syncthreads();

    // ============ encoder: 512 phases (layer0 t=u, layer1 t=u-1) ============
    for (int u = 0; u < 512; u++) {
        if (u > 0) {
            gwait(g, 16u*(unsigned)u);
            // async refresh: h0 (group A) then h1 (group B)
            const float4* s0 = (const float4*)(d_h0g + ((((u&1)^1)*NG + g) << 13));
            const float4* s1 = (const float4*)(d_h1g + ((((u&1)^1)*NG + g) << 13));
#pragma unroll
            for (int i = 0; i < 8; i++) CP16(h0u + tid*16 + i*4096, s0 + tid + i*256);
            CPCOMMIT();
#pragma unroll
            for (int i = 0; i < 8; i++) CP16(h1u + tid*16 + i*4096, s1 + tid + i*256);
            CPCOMMIT();
            CPWAIT(1);          // h0 ready; h1 still in flight
            __syncthreads();
        }

        // ---- loop1: aA (Whh0 @ h0) and aI (Wih1 @ h0) ----
        ull aA[12], aI[12];
#pragma unroll
        for (int i = 0; i < 12; i++) { aA[i] = 0ull; aI[i] = 0ull; }
        {
            const float4* h0p = (const float4*)(h0s + kh*32 + bq*4);
            const ulonglong2* w1p = (const ulonglong2*)(sP1 + kh*100 + cp*12);
            float4 hq = *h0p;
            ulonglong2 p0 = w1p[0], p1 = w1p[1], p2 = w1p[2];
#pragma unroll 4
            for (int kk = 0; kk < 64; kk++) {
                float4 hc = hq;
                ulonglong2 q0 = p0, q1 = p1, q2 = p2;
                if (kk != 63) {
                    h0p += 32; w1p += 100;
                    hq = *h0p; p0 = w1p[0]; p1 = w1p[1]; p2 = w1p[2];
                }
                const float* hf = (const float*)&hc;
#pragma unroll
                for (int bl = 0; bl < 4; bl++) {
                    ull hx = splat2(hf[bl]);
                    fma2(aA[0+bl], q0.x, hx);
                    fma2(aA[4+bl], q0.y, hx);
                    fma2(aA[8+bl], q1.x, hx);
                    fma2(aI[0+bl], q1.y, hx);
                    fma2(aI[4+bl], q2.x, hx);
                    fma2(aI[8+bl], q2.y, hx);
                }
            }
        }
#pragma unroll
        for (int i = 0; i < 12; i++) { aA[i] = shred(aA[i]); aI[i] = shred(aI[i]); }

        // ---- layer0 epilogue (overlaps h1 cp.async): h0(u+1) ----
        if (epi) {
            float4 xv4 = *(const float4*)(d_xT + u*256 + g*32 + bq*4);
            const float* xf = (const float*)&xv4;
            float hv0[4], hv1[4];
#pragma unroll
            for (int bl = 0; bl < 4; bl++) {
                float xv = xf[bl];
                float2 fr = unp(aA[0+bl]), fz = unp(aA[4+bl]), fn = unp(aA[8+bl]);
                {
                    float r  = sigf(xv*wi0[0] + bi0[0] + fr.x + bh0[0]);
                    float zz = sigf(xv*wi0[2] + bi0[2] + fz.x + bh0[2]);
                    float n  = tanh_(xv*wi0[4] + bi0[4] + r*(fn.x + bh0[4]));
                    float hold = h0s[c0*32 + bq*4 + bl];
                    hv0[bl] = (1.0f - zz)*n + zz*hold;
                }
                {
                    float r  = sigf(xv*wi0[1] + bi0[1] + fr.y + bh0[1]);
                    float zz = sigf(xv*wi0[3] + bi0[3] + fz.y + bh0[3]);
                    float n  = tanh_(xv*wi0[5] + bi0[5] + r*(fn.y + bh0[5]));
                    float hold = h0s[(c0+1)*32 + bq*4 + bl];
                    hv1[bl] = (1.0f - zz)*n + zz*hold;
                }
            }
            float* dst = d_h0g + (((u&1)*NG + g) << 13) + c0*32 + bq*4;
            *(float4*)dst        = make_float4(hv0[0], hv0[1], hv0[2], hv0[3]);
            *(float4*)(dst + 32) = make_float4(hv1[0], hv1[1], hv1[2], hv1[3]);
        }

        CPWAIT(0);              // h1 ready
        __syncthreads();

        // ---- loop2: aH (Whh1 @ h1) ----
        ull aH[12];
#pragma unroll
        for (int i = 0; i < 12; i++) aH[i] = 0ull;
        {
            const float4* h1p = (const float4*)(h1s + kh*32 + bq*4);
            const ull* w2p = (const ull*)(sP2 + kh*50 + cp*6);
            float4 hq = *h1p;
            ull r0 = w2p[0], r1 = w2p[1], r2 = w2p[2];
#pragma unroll 4
            for (int kk = 0; kk < 64; kk++) {
                float4 hc = hq;
                ull q0 = r0, q1 = r1, q2 = r2;
                if (kk != 63) {
                    h1p += 32; w2p += 100;
                    hq = *h1p; r0 = w2p[0]; r1 = w2p[1]; r2 = w2p[2];
                }
                const float* hf = (const float*)&hc;
#pragma unroll
                for (int bl = 0; bl < 4; bl++) {
                    ull vx = splat2(hf[bl]);
                    fma2(aH[0+bl], q0, vx);
                    fma2(aH[4+bl], q1, vx);
                    fma2(aH[8+bl], q2, vx);
                }
            }
        }
#pragma unroll
        for (int i = 0; i < 12; i++) aH[i] = shred(aH[i]);

        // ---- layer1 epilogue: h1(u) (skip at u==0) ----
        if (epi && u != 0) {
            float hv0[4], hv1[4];
#pragma unroll
            for (int bl = 0; bl < 4; bl++) {
                float2 fir = unp(aI[0+bl]), fiz = unp(aI[4+bl]), fin = unp(aI[8+bl]);
                float2 fhr = unp(aH[0+bl]), fhz = unp(aH[4+bl]), fhn = unp(aH[8+bl]);
                {
                    float r  = sigf(fir.x + bi1c[0] + fhr.x + bh1c[0]);
                    float zz = sigf(fiz.x + bi1c[2] + fhz.x + bh1c[2]);
                    float n  = tanh_(fin.x + bi1c[4] + r*(fhn.x + bh1c[4]));
                    float hold = h1s[c0*32 + bq*4 + bl];
                    hv0[bl] = (1.0f - zz)*n + zz*hold;
                }
                {
                    float r  = sigf(fir.y + bi1c[1] + fhr.y + bh1c[1]);
                    float zz = sigf(fiz.y + bi1c[3] + fhz.y + bh1c[3]);
                    float n  = tanh_(fin.y + bi1c[5] + r*(fhn.y + bh1c[5]));
                    float hold = h1s[(c0+1)*32 + bq*4 + bl];
                    hv1[bl] = (1.0f - zz)*n + zz*hold;
                }
            }
            float* dst = d_h1g + (((u&1)*NG + g) << 13) + c0*32 + bq*4;
            *(float4*)dst        = make_float4(hv0[0], hv0[1], hv0[2], hv0[3]);
            *(float4*)(dst + 32) = make_float4(hv1[0], hv1[1], hv1[2], hv1[3]);
        }
        garrive(g);
    }

    // ============ drain (phase 512): layer1 t=511 -> h1(512) ============
    {
        gwait(g, 16u*512u);
        const float4* s0 = (const float4*)(d_h0g + ((1*NG + g) << 13));   // parity 511&1 = 1
        const float4* s1 = (const float4*)(d_h1g + ((1*NG + g) << 13));
#pragma unroll
        for (int i = 0; i < 8; i++) CP16(h0u + tid*16 + i*4096, s0 + tid + i*256);
#pragma unroll
        for (int i = 0; i < 8; i++) CP16(h1u + tid*16 + i*4096, s1 + tid + i*256);
        CPCOMMIT();
        CPWAIT(0);
        __syncthreads();

        ull aI[12], aH[12];
#pragma unroll
        for (int i = 0; i < 12; i++) { aI[i] = 0ull; aH[i] = 0ull; }
        {
            const float4* h0p = (const float4*)(h0s + kh*32 + bq*4);
            const float4* h1p = (const float4*)(h1s + kh*32 + bq*4);
            const ulonglong2* w1p = (const ulonglong2*)(sP1 + kh*100 + cp*12);
            const ull* w2p = (const ull*)(sP2 + kh*50 + cp*6);
#pragma unroll 4
            for (int kk = 0; kk < 64; kk++) {
                float4 u4 = *h0p; float4 v4 = *h1p;
                ulonglong2 p1 = w1p[1], p2 = w1p[2];
                ull r0 = w2p[0], r1 = w2p[1], r2 = w2p[2];
                const float* uf = (const float*)&u4;
                const float* vf = (const float*)&v4;
#pragma unroll
                for (int bl = 0; bl < 4; bl++) {
                    ull hx = splat2(uf[bl]);
                    fma2(aI[0+bl], p1.y, hx);
                    fma2(aI[4+bl], p2.x, hx);
                    fma2(aI[8+bl], p2.y, hx);
                    ull vx = splat2(vf[bl]);
                    fma2(aH[0+bl], r0, vx);
                    fma2(aH[4+bl], r1, vx);
                    fma2(aH[8+bl], r2, vx);
                }
                h0p += 32; h1p += 32; w1p += 100; w2p += 100;
            }
        }
#pragma unroll
        for (int i = 0; i < 12; i++) { aI[i] = shred(aI[i]); aH[i] = shred(aH[i]); }
        if (epi) {
            float hv0[4], hv1[4];
#pragma unroll
            for (int bl = 0; bl < 4; bl++) {
                float2 fir = unp(aI[0+bl]), fiz = unp(aI[4+bl]), fin = unp(aI[8+bl]);
                float2 fhr = unp(aH[0+bl]), fhz = unp(aH[4+bl]), fhn = unp(aH[8+bl]);
                {
                    float r  = sigf(fir.x + bi1c[0] + fhr.x + bh1c[0]);
                    float zz = sigf(fiz.x + bi1c[2] + fhz.x + bh1c[2]);
                    float n  = tanh_(fin.x + bi1c[4] + r*(fhn.x + bh1c[4]));
                    float hold = h1s[c0*32 + bq*4 + bl];
                    hv0[bl] = (1.0f - zz)*n + zz*hold;
                }
                {
                    float r  = sigf(fir.y + bi1c[1] + fhr.y + bh1c[1]);
                    float zz = sigf(fiz.y + bi1c[3] + fhz.y + bh1c[3]);
                    float n  = tanh_(fin.y + bi1c[5] + r*(fhn.y + bh1c[5]));
                    float hold = h1s[(c0+1)*32 + bq*4 + bl];
                    hv1[bl] = (1.0f - zz)*n + zz*hold;
                }
            }
            float* dst = d_h1g + ((0*NG + g) << 13) + c0*32 + bq*4;   // parity 512&1 = 0
            *(float4*)dst        = make_float4(hv0[0], hv0[1], hv0[2], hv0[3]);
            *(float4*)(dst + 32) = make_float4(hv1[0], hv1[1], hv1[2], hv1[3]);
        }
        garrive(g);
    }

    // ============ decoder setup ============
    {   // overwrite sP2 with packed Wd_hh (all threads finished drain loop2 at garrive's sync)
        const float4* a4 = (const float4*)(d_pD + p*12800);
        float4* da = (float4*)sP2;
        for (int i = tid; i < 3200; i += NT) da[i] = a4[i];
    }
    float wdi[6], bdi[6], bdh[6], wo0, wo1, bov;
#pragma unroll
    for (int q = 0; q < 6; q++) {
        int j = (q >> 1)*256 + c0 + (q & 1);
        wdi[q] = Wdih[j]; bdi[q] = bdih[j]; bdh[q] = bdhh[j];
    }
    wo0 = Wo[c0]; wo1 = Wo[c0 + 1]; bov = bo[0];

    // ============ decoder: 96 phases ============
    for (int t = 0; t < 96; t++) {
        gwait(g, 16u*(unsigned)(513 + t));
        {   // async refresh h1 from parity t&1
            const float4* s1 = (const float4*)(d_h1g + (((t&1)*NG + g) << 13));
#pragma unroll
            for (int i = 0; i < 8; i++) CP16(h1u + tid*16 + i*4096, s1 + tid + i*256);
            CPCOMMIT();
        }
        if (t > 0 && tid < 32) {   // reduce partials(t-1) -> y(t-1); overlaps cp.async
            float s = bov;
#pragma unroll
            for (int q = 0; q < 16; q++)
                s += __ldcg(&d_party[((((t-1)&1)*NP + q)*NG + g)*32 + tid]);
            ybuf[tid] = s;
            if (p == 0) out[(g*32 + tid)*96 + (t-1)] = s;
        }
        CPWAIT(0);
        __syncthreads();

        float inp[4] = {0.f, 0.f, 0.f, 0.f};
        if (epi && t > 0) {
#pragma unroll
            for (int bl = 0; bl < 4; bl++) inp[bl] = ybuf[bq*4 + bl];
        }

        ull aD[12];
#pragma unroll
        for (int i = 0; i < 12; i++) aD[i] = 0ull;
        {
            const float4* h1p = (const float4*)(h1s + kh*32 + bq*4);
            const ull* w2p = (const ull*)(sP2 + kh*50 + cp*6);
            float4 hq = *h1p;
            ull r0 = w2p[0], r1 = w2p[1], r2 = w2p[2];
#pragma unroll 4
            for (int kk = 0; kk < 64; kk++) {
                float4 hc = hq;
                ull q0 = r0, q1 = r1, q2 = r2;
                if (kk != 63) {
                    h1p += 32; w2p += 100;
                    hq = *h1p; r0 = w2p[0]; r1 = w2p[1]; r2 = w2p[2];
                }
                const float* hf = (const float*)&hc;
#pragma unroll
                for (int bl = 0; bl < 4; bl++) {
                    ull vx = splat2(hf[bl]);
                    fma2(aD[0+bl], q0, vx);
                    fma2(aD[4+bl], q1, vx);
                    fma2(aD[8+bl], q2, vx);
                }
            }
        }
#pragma unroll
        for (int i = 0; i < 12; i++) aD[i] = shred(aD[i]);

        if (epi) {
            float hv0[4], hv1[4];
#pragma unroll
            for (int bl = 0; bl < 4; bl++) {
                float iv = inp[bl];
                float2 fr = unp(aD[0+bl]), fz = unp(aD[4+bl]), fn = unp(aD[8+bl]);
                {
                    float r  = sigf(iv*wdi[0] + bdi[0] + fr.x + bdh[0]);
                    float zz = sigf(iv*wdi[2] + bdi[2] + fz.x + bdh[2]);
                    float n  = tanh_(iv*wdi[4] + bdi[4] + r*(fn.x + bdh[4]));
                    float hold = h1s[c0*32 + bq*4 + bl];
                    hv0[bl] = (1.0f - zz)*n + zz*hold;
                }
                {
                    float r  = sigf(iv*wdi[1] + bdi[1] + fr.y + bdh[1]);
                    float zz = sigf(iv*wdi[3] + bdi[3] + fz.y + bdh[3]);
                    float n  = tanh_(iv*wdi[5] + bdi[5] + r*(fn.y + bdh[5]));
                    float hold = h1s[(c0+1)*32 + bq*4 + bl];
                    hv1[bl] = (1.0f - zz)*n + zz*hold;
                }
                red2[(bq*4 + bl)*8 + cp] = hv0[bl]*wo0 + hv1[bl]*wo1;
            }
            float* dst = d_h1g + ((((t+1)&1)*NG + g) << 13) + c0*32 + bq*4;
            *(float4*)dst        = make_float4(hv0[0], hv0[1], hv0[2], hv0[3]);
            *(float4*)(dst + 32) = make_float4(hv1[0], hv1[1], hv1[2], hv1[3]);
        }
        __syncthreads();
        if (tid < 32) {   // partial over this CTA's 16 cols (fixed order), parity t&1
            float s = 0.f;
#pragma unroll
            for (int j = 0; j < 8; j++) s += red2[tid*8 + j];
            d_party[(((t&1)*NP + p)*NG + g)*32 + tid] = s;
        }
        garrive(g);
    }

    // final output (t = 95): partials at parity 1
    gwait(g, 16u*609u);
    if (p == 0 && tid < 32) {
        float s = bov;
#pragma unroll
        for (int q = 0; q < 16; q++)
            s += __ldcg(&d_party[((1*NP + q)*NG + g)*32 + tid]);
        out[(g*32 + tid)*96 + 95] = s;
    }
}

// ---------------- launch ----------------
extern "C" void kernel_launch(void* const* d_in, const int* in_sizes, int n_in,
                              void* d_out, int out_size)
{
    const float* x    = (const float*)d_in[0];
    const float* Wih0 = (const float*)d_in[1];
    const float* Whh0 = (const float*)d_in[2];
    const float* bih0 = (const float*)d_in[3];
    const float* bhh0 = (const float*)d_in[4];
    const float* Wih1 = (const float*)d_in[5];
    const float* Whh1 = (const float*)d_in[6];
    const float* bih1 = (const float*)d_in[7];
    const float* bhh1 = (const float*)d_in[8];
    const float* Wdih = (const float*)d_in[9];
    const float* Wdhh = (const float*)d_in[10];
    const float* bdih = (const float*)d_in[11];
    const float* bdhh = (const float*)d_in[12];
    const float* Wo   = (const float*)d_in[13];
    const float* bo   = (const float*)d_in[14];
    float* out = (float*)d_out;

    cudaFuncSetAttribute(gru_main, cudaFuncAttributeMaxDynamicSharedMemorySize, SMEM_BYTES);
    prep_kernel<<<384, 256>>>(Whh0, Wih1, Whh1, Wdhh, x);
    gru_main<<<NBLK, NT, SMEM_BYTES>>>(Wih0, bih0, bhh0, bih1, bhh1,
                                       Wdih, bdih, bdhh, Wo, bo, out);
}